// round 2
// baseline (speedup 1.0000x reference)
#include <cuda_runtime.h>
#include <stdint.h>

#define BLOCK 256
#define SEG 8
#define CHUNK (BLOCK * SEG)          // 2048
#define MAXN (1 << 22)               // 4M capacity (N is 2M)
#define MAXCH (MAXN / CHUNK)

#define GAMMA_F 0.99f
#define LAMBDA_F 0.95f
#define CLIP_EPS_F 0.2f

// ---- device scratch (no allocations allowed) ----
__device__ float  g_adv[MAXN];
__device__ float  g_aggC[MAXCH];
__device__ float  g_aggD[MAXCH];
__device__ float  g_incv[MAXCH];
__device__ int    g_aggFlag[MAXCH];
__device__ int    g_incFlag[MAXCH];
__device__ int    g_ticket;
__device__ double g_sum;
__device__ double g_sumsq;
__device__ float  g_mean;
__device__ float  g_rinv;
__device__ int    g_boolByteLayout;   // 1 = bools are 1 byte each, 0 = int32

// ---- detect bool storage layout (deterministic given fixed inputs) ----
__global__ void detect_layout_kernel(const uint8_t* __restrict__ t1,
                                     const uint8_t* __restrict__ t2, int n) {
    __shared__ int found;
    if (threadIdx.x == 0) found = 0;
    __syncthreads();
    int limit = n < 65536 ? n : 65536;   // bytes; safe under both layouts
    for (int i = threadIdx.x; i < limit; i += blockDim.x) {
        if ((i & 3) != 0 && (t1[i] | t2[i])) found = 1;
    }
    __syncthreads();
    if (threadIdx.x == 0) g_boolByteLayout = found;
}

// ---- reset per replay (graph-capturable) ----
__global__ void init_kernel(int numChunks) {
    int i = blockIdx.x * blockDim.x + threadIdx.x;
    if (i < numChunks) { g_aggFlag[i] = 0; g_incFlag[i] = 0; }
    if (i == 0) { g_ticket = 0; g_sum = 0.0; g_sumsq = 0.0; }
}

// ---- single-pass reverse scan with decoupled lookback ----
__global__ __launch_bounds__(BLOCK)
void gae_scan_kernel(const float* __restrict__ rewards,
                     const float* __restrict__ values,
                     const float* __restrict__ next_values,
                     const void* __restrict__ terminated_raw,
                     const void* __restrict__ truncated_raw,
                     int n, int numChunks)
{
    __shared__ float sC[BLOCK + 1];
    __shared__ float sD[BLOCK + 1];
    __shared__ float s_incoming;
    __shared__ int   s_chunk;
    __shared__ double s_wsum[BLOCK / 32];
    __shared__ double s_wsq[BLOCK / 32];

    const int t = threadIdx.x;
    if (t == 0) s_chunk = numChunks - 1 - atomicAdd(&g_ticket, 1);
    __syncthreads();
    const int chunk = s_chunk;
    const long long base = (long long)chunk * CHUNK + (long long)t * SEG;
    const int byteLayout = g_boolByteLayout;

    const float GL = GAMMA_F * LAMBDA_F;
    float cc[SEG], dd[SEG];

    const bool full = (base + SEG <= (long long)n);
    if (full) {
        float rr[SEG], vv[SEG], nn[SEG];
        *(float4*)(rr)     = __ldg((const float4*)(rewards + base));
        *(float4*)(rr + 4) = __ldg((const float4*)(rewards + base) + 1);
        *(float4*)(vv)     = __ldg((const float4*)(values + base));
        *(float4*)(vv + 4) = __ldg((const float4*)(values + base) + 1);
        *(float4*)(nn)     = __ldg((const float4*)(next_values + base));
        *(float4*)(nn + 4) = __ldg((const float4*)(next_values + base) + 1);

        int te8[SEG], tu8[SEG];
        if (byteLayout) {
            unsigned long long tm = *(const unsigned long long*)((const uint8_t*)terminated_raw + base);
            unsigned long long tr = *(const unsigned long long*)((const uint8_t*)truncated_raw + base);
#pragma unroll
            for (int j = 0; j < SEG; j++) {
                te8[j] = (int)((tm >> (8 * j)) & 0xFFull);
                tu8[j] = (int)((tr >> (8 * j)) & 0xFFull);
            }
        } else {
            const int4* tm4 = (const int4*)((const int*)terminated_raw + base);
            const int4* tr4 = (const int4*)((const int*)truncated_raw + base);
            int4 a0 = __ldg(tm4), a1 = __ldg(tm4 + 1);
            int4 b0 = __ldg(tr4), b1 = __ldg(tr4 + 1);
            te8[0]=a0.x; te8[1]=a0.y; te8[2]=a0.z; te8[3]=a0.w;
            te8[4]=a1.x; te8[5]=a1.y; te8[6]=a1.z; te8[7]=a1.w;
            tu8[0]=b0.x; tu8[1]=b0.y; tu8[2]=b0.z; tu8[3]=b0.w;
            tu8[4]=b1.x; tu8[5]=b1.y; tu8[6]=b1.z; tu8[7]=b1.w;
        }
#pragma unroll
        for (int j = 0; j < SEG; j++) {
            bool te = te8[j] != 0;
            bool tu = tu8[j] != 0;
            float nt = te ? 0.f : 1.f;
            dd[j] = rr[j] + GAMMA_F * nt * nn[j] - vv[j];
            cc[j] = (te || tu) ? 0.f : GL;
        }
    } else {
#pragma unroll
        for (int j = 0; j < SEG; j++) {
            long long idx = base + j;
            if (idx < (long long)n) {
                bool te, tu;
                if (byteLayout) {
                    te = ((const uint8_t*)terminated_raw)[idx] != 0;
                    tu = ((const uint8_t*)truncated_raw)[idx] != 0;
                } else {
                    te = ((const int*)terminated_raw)[idx] != 0;
                    tu = ((const int*)truncated_raw)[idx] != 0;
                }
                float nt = te ? 0.f : 1.f;
                dd[j] = rewards[idx] + GAMMA_F * nt * next_values[idx] - values[idx];
                cc[j] = (te || tu) ? 0.f : GL;
            } else { cc[j] = 1.f; dd[j] = 0.f; }
        }
    }

    // per-thread segment composition (reverse): (C,D) maps adv-after-segment -> adv-at-segment-start
    float C = 1.f, D = 0.f;
#pragma unroll
    for (int j = SEG - 1; j >= 0; j--) { D = cc[j] * D + dd[j]; C = cc[j] * C; }

    // inclusive suffix scan over threads (Hillis-Steele); incl[t] = f_t o ... o f_{BLOCK-1}
    sC[t] = C; sD[t] = D;
    __syncthreads();
#pragma unroll
    for (int off = 1; off < BLOCK; off <<= 1) {
        float nc, nd;
        if (t + off < BLOCK) { nc = sC[t] * sC[t + off]; nd = sC[t] * sD[t + off] + sD[t]; }
        else                 { nc = sC[t]; nd = sD[t]; }
        __syncthreads();
        sC[t] = nc; sD[t] = nd;
        __syncthreads();
    }

    // thread 0: publish aggregate, lookback for incoming value, publish inclusive
    if (t == 0) {
        float bC = sC[0], bD = sD[0];
        g_aggC[chunk] = bC; g_aggD[chunk] = bD;
        __threadfence();
        atomicExch(&g_aggFlag[chunk], 1);
        if (bC == 0.f) {  // inclusive independent of incoming -> publish immediately
            g_incv[chunk] = bD;
            __threadfence();
            atomicExch(&g_incFlag[chunk], 1);
        }
        float incoming = 0.f;
        if (chunk < numChunks - 1) {
            float aC = 1.f, aD = 0.f;
            int j = chunk + 1;
            for (;;) {
                if (atomicAdd(&g_incFlag[j], 0) != 0) {
                    __threadfence();
                    incoming = aC * ((volatile float*)g_incv)[j] + aD;
                    break;
                }
                if (atomicAdd(&g_aggFlag[j], 0) != 0) {
                    __threadfence();
                    float jc = ((volatile float*)g_aggC)[j];
                    float jd = ((volatile float*)g_aggD)[j];
                    aD = aC * jd + aD;
                    aC = aC * jc;
                    if (aC == 0.f || j == numChunks - 1) { incoming = aD; break; }
                    j++;
                }
            }
        }
        if (bC != 0.f) {
            g_incv[chunk] = bC * incoming + bD;
            __threadfence();
            atomicExch(&g_incFlag[chunk], 1);
        }
        s_incoming = incoming;
        sC[BLOCK] = 1.f; sD[BLOCK] = 0.f;
    }
    __syncthreads();

    // per-thread: x = adv value right after this segment = incl[t+1](incoming)
    float x = sC[t + 1] * s_incoming + sD[t + 1];
    float outv[SEG];
    float lsum = 0.f, lsq = 0.f;
    if (full) {
#pragma unroll
        for (int j = SEG - 1; j >= 0; j--) {
            x = cc[j] * x + dd[j];
            outv[j] = x;
            lsum += x; lsq += x * x;
        }
        *(float4*)(g_adv + base)     = make_float4(outv[0], outv[1], outv[2], outv[3]);
        *(float4*)(g_adv + base + 4) = make_float4(outv[4], outv[5], outv[6], outv[7]);
    } else {
#pragma unroll
        for (int j = SEG - 1; j >= 0; j--) {
            x = cc[j] * x + dd[j];
            long long idx = base + j;
            if (idx < (long long)n) {
                g_adv[idx] = x;
                lsum += x; lsq += x * x;
            }
        }
    }

    // block reduce (double) -> global atomics
    double ds = (double)lsum, dq = (double)lsq;
#pragma unroll
    for (int o = 16; o > 0; o >>= 1) {
        ds += __shfl_down_sync(0xFFFFFFFFu, ds, o);
        dq += __shfl_down_sync(0xFFFFFFFFu, dq, o);
    }
    int lane = t & 31, wid = t >> 5;
    if (lane == 0) { s_wsum[wid] = ds; s_wsq[wid] = dq; }
    __syncthreads();
    if (t == 0) {
        double ts = 0.0, tq = 0.0;
#pragma unroll
        for (int w = 0; w < BLOCK / 32; w++) { ts += s_wsum[w]; tq += s_wsq[w]; }
        atomicAdd(&g_sum, ts);
        atomicAdd(&g_sumsq, tq);
    }
}

__global__ void finalize_stats(int n) {
    double s = g_sum, q = g_sumsq;
    double mean = s / (double)n;
    double var = (q - s * s / (double)n) / (double)(n - 1);
    if (var < 0.0) var = 0.0;
    g_mean = (float)mean;
    g_rinv = (float)(1.0 / (sqrt(var) + 1e-9));
}

__device__ __forceinline__ void ppo_row(float a, float v, float lp, float olp,
                                        float mean, float rinv, float* o) {
    float an = (a - mean) * rinv;
    float lr = a + v;
    float ratio = expf(lp - olp);
    float cl = fminf(fmaxf(ratio, 1.f - CLIP_EPS_F), 1.f + CLIP_EPS_F);
    float loss = -fminf(ratio * an, cl * an);
    o[0] = an; o[1] = lr; o[2] = loss;
}

__global__ __launch_bounds__(256)
void output_kernel(const float* __restrict__ values,
                   const float* __restrict__ log_probs,
                   const float* __restrict__ old_log_probs,
                   float* __restrict__ out, int n)
{
    const float mean = g_mean, rinv = g_rinv;
    long long base = ((long long)blockIdx.x * blockDim.x + threadIdx.x) * 4;
    if (base + 4 <= (long long)n) {
        float4 a   = *(const float4*)(g_adv + base);
        float4 v   = __ldg((const float4*)(values + base));
        float4 lp  = __ldg((const float4*)(log_probs + base));
        float4 olp = __ldg((const float4*)(old_log_probs + base));
        float o[12];
        ppo_row(a.x, v.x, lp.x, olp.x, mean, rinv, o + 0);
        ppo_row(a.y, v.y, lp.y, olp.y, mean, rinv, o + 3);
        ppo_row(a.z, v.z, lp.z, olp.z, mean, rinv, o + 6);
        ppo_row(a.w, v.w, lp.w, olp.w, mean, rinv, o + 9);
        float4* dst = (float4*)(out + base * 3);
        dst[0] = make_float4(o[0], o[1], o[2], o[3]);
        dst[1] = make_float4(o[4], o[5], o[6], o[7]);
        dst[2] = make_float4(o[8], o[9], o[10], o[11]);
    } else {
        for (long long i = base; i < (long long)n; i++) {
            float o[3];
            ppo_row(g_adv[i], values[i], log_probs[i], old_log_probs[i], mean, rinv, o);
            out[i * 3 + 0] = o[0];
            out[i * 3 + 1] = o[1];
            out[i * 3 + 2] = o[2];
        }
    }
}

extern "C" void kernel_launch(void* const* d_in, const int* in_sizes, int n_in,
                              void* d_out, int out_size) {
    const float*   rewards       = (const float*)d_in[0];
    const float*   values        = (const float*)d_in[1];
    const float*   next_values   = (const float*)d_in[2];
    const float*   log_probs     = (const float*)d_in[3];
    const float*   old_log_probs = (const float*)d_in[4];
    const void*    terminated    = d_in[5];
    const void*    truncated     = d_in[6];
    float* out = (float*)d_out;

    int n = in_sizes[0];
    int numChunks = (n + CHUNK - 1) / CHUNK;

    detect_layout_kernel<<<1, 256>>>((const uint8_t*)terminated, (const uint8_t*)truncated, n);
    init_kernel<<<(numChunks + 255) / 256, 256>>>(numChunks);
    gae_scan_kernel<<<numChunks, BLOCK>>>(rewards, values, next_values,
                                          terminated, truncated, n, numChunks);
    finalize_stats<<<1, 1>>>(n);
    int nv4 = (n + 3) / 4;
    output_kernel<<<(nv4 + 255) / 256, 256>>>(values, log_probs, old_log_probs, out, n);
}

// round 3
// speedup vs baseline: 2.7174x; 2.7174x over previous
#include <cuda_runtime.h>
#include <stdint.h>

#define BLOCK 256
#define SEG 8
#define CHUNK (BLOCK * SEG)          // 2048
#define MAXN (1 << 22)
#define MAXCH (MAXN / CHUNK)
#define GRID 512                     // persistent blocks; 4/SM * 148 SMs = 592 >= 512

#define GAMMA_F 0.99f
#define LAMBDA_F 0.95f
#define CLIP_EPS_F 0.2f

// ---- device scratch ----
__device__ float  g_adv[MAXN];
__device__ float  g_aggC[MAXCH];
__device__ float  g_aggD[MAXCH];
__device__ float  g_incv[MAXCH];
__device__ int    g_aggFlag[MAXCH];
__device__ int    g_incFlag[MAXCH];
__device__ int    g_ticket;
__device__ int    g_done;
__device__ double g_sum;
__device__ double g_sumsq;
__device__ int    g_boolByteLayout;

// ---- init: reset state + detect bool layout (fused, 1 launch) ----
__global__ void init_kernel(const uint8_t* __restrict__ t1,
                            const uint8_t* __restrict__ t2,
                            int n, int numChunks) {
    int i = blockIdx.x * blockDim.x + threadIdx.x;
    if (i < numChunks) { g_aggFlag[i] = 0; g_incFlag[i] = 0; }
    if (i == 0) { g_ticket = 0; g_done = 0; g_sum = 0.0; g_sumsq = 0.0; }
    // block 0: layout detection over first 16KB (bytes at offset%4!=0 nonzero => byte layout)
    if (blockIdx.x == 0) {
        __shared__ int found;
        if (threadIdx.x == 0) found = 0;
        __syncthreads();
        int limit16 = (n < 16384 ? n : 16384) / 16;   // uint4 count
        const uint4* a = (const uint4*)t1;
        const uint4* b = (const uint4*)t2;
        unsigned acc = 0;
        for (int k = threadIdx.x; k < limit16; k += blockDim.x) {
            uint4 x = a[k], y = b[k];
            acc |= (x.x | x.y | x.z | x.w | y.x | y.y | y.z | y.w) & 0xFFFFFF00u;
        }
        if (acc) found = 1;
        __syncthreads();
        if (threadIdx.x == 0) g_boolByteLayout = found;
    }
}

__device__ __forceinline__ void ppo_row(float a, float v, float lp, float olp,
                                        float mean, float rinv, float* o) {
    float an = (a - mean) * rinv;
    float lr = a + v;
    float ratio = __expf(lp - olp);
    float cl = fminf(fmaxf(ratio, 1.f - CLIP_EPS_F), 1.f + CLIP_EPS_F);
    float loss = -fminf(ratio * an, cl * an);
    o[0] = an; o[1] = lr; o[2] = loss;
}

// ---- fused persistent kernel: scan -> grid barrier -> stats -> epilogue ----
__global__ __launch_bounds__(BLOCK, 4)
void fused_kernel(const float* __restrict__ rewards,
                  const float* __restrict__ values,
                  const float* __restrict__ next_values,
                  const float* __restrict__ log_probs,
                  const float* __restrict__ old_log_probs,
                  const void* __restrict__ terminated_raw,
                  const void* __restrict__ truncated_raw,
                  float* __restrict__ out,
                  int n, int numChunks)
{
    __shared__ float sC[BLOCK + 1];
    __shared__ float sD[BLOCK + 1];
    __shared__ float s_incoming;
    __shared__ int   s_chunk;
    __shared__ float s_mean, s_rinv;
    __shared__ double s_wsum[BLOCK / 32];
    __shared__ double s_wsq[BLOCK / 32];

    const int t = threadIdx.x;
    const int byteLayout = g_boolByteLayout;
    const float GL = GAMMA_F * LAMBDA_F;

    float accSum = 0.f, accSq = 0.f;

    // ===== phase 1: reverse scan over chunks (ticket order = reverse) =====
    for (;;) {
        if (t == 0) {
            int tk = atomicAdd(&g_ticket, 1);
            s_chunk = (tk < numChunks) ? (numChunks - 1 - tk) : -1;
        }
        __syncthreads();
        const int chunk = s_chunk;
        if (chunk < 0) break;
        const long long base = (long long)chunk * CHUNK + (long long)t * SEG;

        float cc[SEG], dd[SEG];
        const bool full = (base + SEG <= (long long)n);
        if (full) {
            float rr[SEG], vv[SEG], nn[SEG];
            *(float4*)(rr)     = __ldg((const float4*)(rewards + base));
            *(float4*)(rr + 4) = __ldg((const float4*)(rewards + base) + 1);
            *(float4*)(vv)     = __ldg((const float4*)(values + base));
            *(float4*)(vv + 4) = __ldg((const float4*)(values + base) + 1);
            *(float4*)(nn)     = __ldg((const float4*)(next_values + base));
            *(float4*)(nn + 4) = __ldg((const float4*)(next_values + base) + 1);

            int te8[SEG], tu8[SEG];
            if (byteLayout) {
                unsigned long long tm = *(const unsigned long long*)((const uint8_t*)terminated_raw + base);
                unsigned long long tr = *(const unsigned long long*)((const uint8_t*)truncated_raw + base);
#pragma unroll
                for (int j = 0; j < SEG; j++) {
                    te8[j] = (int)((tm >> (8 * j)) & 0xFFull);
                    tu8[j] = (int)((tr >> (8 * j)) & 0xFFull);
                }
            } else {
                const int4* tm4 = (const int4*)((const int*)terminated_raw + base);
                const int4* tr4 = (const int4*)((const int*)truncated_raw + base);
                int4 a0 = __ldg(tm4), a1 = __ldg(tm4 + 1);
                int4 b0 = __ldg(tr4), b1 = __ldg(tr4 + 1);
                te8[0]=a0.x; te8[1]=a0.y; te8[2]=a0.z; te8[3]=a0.w;
                te8[4]=a1.x; te8[5]=a1.y; te8[6]=a1.z; te8[7]=a1.w;
                tu8[0]=b0.x; tu8[1]=b0.y; tu8[2]=b0.z; tu8[3]=b0.w;
                tu8[4]=b1.x; tu8[5]=b1.y; tu8[6]=b1.z; tu8[7]=b1.w;
            }
#pragma unroll
            for (int j = 0; j < SEG; j++) {
                bool te = te8[j] != 0;
                bool tu = tu8[j] != 0;
                float nt = te ? 0.f : 1.f;
                dd[j] = rr[j] + GAMMA_F * nt * nn[j] - vv[j];
                cc[j] = (te || tu) ? 0.f : GL;
            }
        } else {
#pragma unroll
            for (int j = 0; j < SEG; j++) {
                long long idx = base + j;
                if (idx < (long long)n) {
                    bool te, tu;
                    if (byteLayout) {
                        te = ((const uint8_t*)terminated_raw)[idx] != 0;
                        tu = ((const uint8_t*)truncated_raw)[idx] != 0;
                    } else {
                        te = ((const int*)terminated_raw)[idx] != 0;
                        tu = ((const int*)truncated_raw)[idx] != 0;
                    }
                    float nt = te ? 0.f : 1.f;
                    dd[j] = rewards[idx] + GAMMA_F * nt * next_values[idx] - values[idx];
                    cc[j] = (te || tu) ? 0.f : GL;
                } else { cc[j] = 1.f; dd[j] = 0.f; }
            }
        }

        float C = 1.f, D = 0.f;
#pragma unroll
        for (int j = SEG - 1; j >= 0; j--) { D = cc[j] * D + dd[j]; C = cc[j] * C; }

        sC[t] = C; sD[t] = D;
        __syncthreads();
#pragma unroll
        for (int off = 1; off < BLOCK; off <<= 1) {
            float nc, nd;
            if (t + off < BLOCK) { nc = sC[t] * sC[t + off]; nd = sC[t] * sD[t + off] + sD[t]; }
            else                 { nc = sC[t]; nd = sD[t]; }
            __syncthreads();
            sC[t] = nc; sD[t] = nd;
            __syncthreads();
        }

        if (t == 0) {
            float bC = sC[0], bD = sD[0];
            g_aggC[chunk] = bC; g_aggD[chunk] = bD;
            __threadfence();
            atomicExch(&g_aggFlag[chunk], 1);
            if (bC == 0.f) {
                g_incv[chunk] = bD;
                __threadfence();
                atomicExch(&g_incFlag[chunk], 1);
            }
            float incoming = 0.f;
            if (chunk < numChunks - 1) {
                float aC = 1.f, aD = 0.f;
                int j = chunk + 1;
                for (;;) {
                    if (atomicAdd(&g_incFlag[j], 0) != 0) {
                        __threadfence();
                        incoming = aC * ((volatile float*)g_incv)[j] + aD;
                        break;
                    }
                    if (atomicAdd(&g_aggFlag[j], 0) != 0) {
                        __threadfence();
                        float jc = ((volatile float*)g_aggC)[j];
                        float jd = ((volatile float*)g_aggD)[j];
                        aD = aC * jd + aD;
                        aC = aC * jc;
                        if (aC == 0.f || j == numChunks - 1) { incoming = aD; break; }
                        j++;
                    }
                }
            }
            if (bC != 0.f) {
                g_incv[chunk] = bC * incoming + bD;
                __threadfence();
                atomicExch(&g_incFlag[chunk], 1);
            }
            s_incoming = incoming;
            sC[BLOCK] = 1.f; sD[BLOCK] = 0.f;
        }
        __syncthreads();

        float x = sC[t + 1] * s_incoming + sD[t + 1];
        if (full) {
            float outv[SEG];
#pragma unroll
            for (int j = SEG - 1; j >= 0; j--) {
                x = cc[j] * x + dd[j];
                outv[j] = x;
                accSum += x; accSq += x * x;
            }
            *(float4*)(g_adv + base)     = make_float4(outv[0], outv[1], outv[2], outv[3]);
            *(float4*)(g_adv + base + 4) = make_float4(outv[4], outv[5], outv[6], outv[7]);
        } else {
#pragma unroll
            for (int j = SEG - 1; j >= 0; j--) {
                x = cc[j] * x + dd[j];
                long long idx = base + j;
                if (idx < (long long)n) {
                    g_adv[idx] = x;
                    accSum += x; accSq += x * x;
                }
            }
        }
    }

    // block reduce sums -> global atomics
    {
        double ds = (double)accSum, dq = (double)accSq;
#pragma unroll
        for (int o = 16; o > 0; o >>= 1) {
            ds += __shfl_down_sync(0xFFFFFFFFu, ds, o);
            dq += __shfl_down_sync(0xFFFFFFFFu, dq, o);
        }
        int lane = t & 31, wid = t >> 5;
        if (lane == 0) { s_wsum[wid] = ds; s_wsq[wid] = dq; }
        __syncthreads();
        if (t == 0) {
            double ts = 0.0, tq = 0.0;
#pragma unroll
            for (int w = 0; w < BLOCK / 32; w++) { ts += s_wsum[w]; tq += s_wsq[w]; }
            atomicAdd(&g_sum, ts);
            atomicAdd(&g_sumsq, tq);
        }
    }

    // ===== grid barrier (all GRID blocks are co-resident by launch_bounds) =====
    __threadfence();
    if (t == 0) {
        atomicAdd(&g_done, 1);
        while (atomicAdd(&g_done, 0) < GRID) { }
        __threadfence();
        double s = g_sum, q = g_sumsq;
        double mean = s / (double)n;
        double var = (q - s * s / (double)n) / (double)(n - 1);
        if (var < 0.0) var = 0.0;
        s_mean = (float)mean;
        s_rinv = (float)(1.0 / (sqrt(var) + 1e-9));
    }
    __syncthreads();
    const float mean = s_mean, rinv = s_rinv;

    // ===== phase 2: epilogue (grid-stride, vectorized) =====
    const long long nv4 = n / 4;
    const long long stride = (long long)GRID * BLOCK;
    for (long long i4 = (long long)blockIdx.x * BLOCK + t; i4 < nv4; i4 += stride) {
        long long base = i4 * 4;
        float4 a   = *(const float4*)(g_adv + base);
        float4 v   = __ldg((const float4*)(values + base));
        float4 lp  = __ldg((const float4*)(log_probs + base));
        float4 olp = __ldg((const float4*)(old_log_probs + base));
        float o[12];
        ppo_row(a.x, v.x, lp.x, olp.x, mean, rinv, o + 0);
        ppo_row(a.y, v.y, lp.y, olp.y, mean, rinv, o + 3);
        ppo_row(a.z, v.z, lp.z, olp.z, mean, rinv, o + 6);
        ppo_row(a.w, v.w, lp.w, olp.w, mean, rinv, o + 9);
        float4* dst = (float4*)(out + base * 3);
        dst[0] = make_float4(o[0], o[1], o[2], o[3]);
        dst[1] = make_float4(o[4], o[5], o[6], o[7]);
        dst[2] = make_float4(o[8], o[9], o[10], o[11]);
    }
    // scalar tail
    if (blockIdx.x == 0 && t == 0) {
        for (long long i = nv4 * 4; i < (long long)n; i++) {
            float o[3];
            ppo_row(g_adv[i], values[i], log_probs[i], old_log_probs[i], mean, rinv, o);
            out[i * 3 + 0] = o[0];
            out[i * 3 + 1] = o[1];
            out[i * 3 + 2] = o[2];
        }
    }
}

extern "C" void kernel_launch(void* const* d_in, const int* in_sizes, int n_in,
                              void* d_out, int out_size) {
    const float* rewards       = (const float*)d_in[0];
    const float* values        = (const float*)d_in[1];
    const float* next_values   = (const float*)d_in[2];
    const float* log_probs     = (const float*)d_in[3];
    const float* old_log_probs = (const float*)d_in[4];
    const void*  terminated    = d_in[5];
    const void*  truncated     = d_in[6];
    float* out = (float*)d_out;

    int n = in_sizes[0];
    int numChunks = (n + CHUNK - 1) / CHUNK;

    init_kernel<<<(numChunks + 255) / 256, 256>>>((const uint8_t*)terminated,
                                                  (const uint8_t*)truncated, n, numChunks);
    fused_kernel<<<GRID, BLOCK>>>(rewards, values, next_values,
                                  log_probs, old_log_probs,
                                  terminated, truncated, out, n, numChunks);
}

// round 4
// speedup vs baseline: 2.7987x; 1.0299x over previous
#include <cuda_runtime.h>
#include <stdint.h>

#define BLOCK 256
#define SEG 8
#define CHUNK (BLOCK * SEG)          // 2048
#define MAXN (1 << 22)
#define MAXCH (MAXN / CHUNK)
#define BLOCKS_PER_SM 5
#define GRID (BLOCKS_PER_SM * 148)   // 740: exact wave-1 co-residency

#define GAMMA_F 0.99f
#define LAMBDA_F 0.95f
#define CLIP_EPS_F 0.2f

// ---- device scratch ----
__device__ float  g_adv[MAXN];
__device__ float  g_aggC[MAXCH];
__device__ float  g_aggD[MAXCH];
__device__ float  g_incv[MAXCH];
__device__ int    g_aggFlag[MAXCH];
__device__ int    g_incFlag[MAXCH];
__device__ int    g_ticket;
__device__ int    g_done;
__device__ double g_sum;
__device__ double g_sumsq;
__device__ int    g_boolByteLayout;

// ---- init: reset state + detect bool layout ----
__global__ void init_kernel(const uint8_t* __restrict__ t1,
                            const uint8_t* __restrict__ t2,
                            int n, int numChunks) {
    int i = blockIdx.x * blockDim.x + threadIdx.x;
    if (i < numChunks) { g_aggFlag[i] = 0; g_incFlag[i] = 0; }
    if (i == 0) { g_ticket = 0; g_done = 0; g_sum = 0.0; g_sumsq = 0.0; }
    if (blockIdx.x == 0) {
        __shared__ int found;
        if (threadIdx.x == 0) found = 0;
        __syncthreads();
        int limit16 = (n < 16384 ? n : 16384) / 16;
        const uint4* a = (const uint4*)t1;
        const uint4* b = (const uint4*)t2;
        unsigned acc = 0;
        for (int k = threadIdx.x; k < limit16; k += blockDim.x) {
            uint4 x = a[k], y = b[k];
            acc |= (x.x | x.y | x.z | x.w | y.x | y.y | y.z | y.w) & 0xFFFFFF00u;
        }
        if (acc) found = 1;
        __syncthreads();
        if (threadIdx.x == 0) g_boolByteLayout = found;
    }
}

__device__ __forceinline__ void ppo_row(float a, float v, float lp, float olp,
                                        float mean, float rinv, float* o) {
    float an = (a - mean) * rinv;
    float lr = a + v;
    float ratio = __expf(lp - olp);
    float cl = fminf(fmaxf(ratio, 1.f - CLIP_EPS_F), 1.f + CLIP_EPS_F);
    float loss = -fminf(ratio * an, cl * an);
    o[0] = an; o[1] = lr; o[2] = loss;
}

// ---- fused persistent kernel ----
__global__ __launch_bounds__(BLOCK, BLOCKS_PER_SM)
void fused_kernel(const float* __restrict__ rewards,
                  const float* __restrict__ values,
                  const float* __restrict__ next_values,
                  const float* __restrict__ log_probs,
                  const float* __restrict__ old_log_probs,
                  const void* __restrict__ terminated_raw,
                  const void* __restrict__ truncated_raw,
                  float* __restrict__ out,
                  int n, int numChunks)
{
    __shared__ float  s_aggC[BLOCK / 32];
    __shared__ float  s_aggD[BLOCK / 32];
    __shared__ float  s_incoming;
    __shared__ int    s_chunk;
    __shared__ float  s_mean, s_rinv;
    __shared__ double s_wsum[BLOCK / 32];
    __shared__ double s_wsq[BLOCK / 32];

    const int t = threadIdx.x;
    const int lane = t & 31;
    const int wrp  = t >> 5;
    const int byteLayout = g_boolByteLayout;
    const float GL = GAMMA_F * LAMBDA_F;

    float accSum = 0.f, accSq = 0.f;

    // ===== phase 1: reverse scan over chunks (dynamic tickets) =====
    for (;;) {
        if (t == 0) {
            int tk = atomicAdd(&g_ticket, 1);
            s_chunk = (tk < numChunks) ? (numChunks - 1 - tk) : -1;
        }
        __syncthreads();
        const int chunk = s_chunk;
        if (chunk < 0) break;
        const long long base = (long long)chunk * CHUNK + (long long)t * SEG;

        float cc[SEG], dd[SEG];
        const bool full = (base + SEG <= (long long)n);
        if (full) {
            float rr[SEG], vv[SEG], nn[SEG];
            *(float4*)(rr)     = __ldg((const float4*)(rewards + base));
            *(float4*)(rr + 4) = __ldg((const float4*)(rewards + base) + 1);
            *(float4*)(vv)     = __ldg((const float4*)(values + base));
            *(float4*)(vv + 4) = __ldg((const float4*)(values + base) + 1);
            *(float4*)(nn)     = __ldg((const float4*)(next_values + base));
            *(float4*)(nn + 4) = __ldg((const float4*)(next_values + base) + 1);

            int te8[SEG], tu8[SEG];
            if (byteLayout) {
                unsigned long long tm = *(const unsigned long long*)((const uint8_t*)terminated_raw + base);
                unsigned long long tr = *(const unsigned long long*)((const uint8_t*)truncated_raw + base);
#pragma unroll
                for (int j = 0; j < SEG; j++) {
                    te8[j] = (int)((tm >> (8 * j)) & 0xFFull);
                    tu8[j] = (int)((tr >> (8 * j)) & 0xFFull);
                }
            } else {
                const int4* tm4 = (const int4*)((const int*)terminated_raw + base);
                const int4* tr4 = (const int4*)((const int*)truncated_raw + base);
                int4 a0 = __ldg(tm4), a1 = __ldg(tm4 + 1);
                int4 b0 = __ldg(tr4), b1 = __ldg(tr4 + 1);
                te8[0]=a0.x; te8[1]=a0.y; te8[2]=a0.z; te8[3]=a0.w;
                te8[4]=a1.x; te8[5]=a1.y; te8[6]=a1.z; te8[7]=a1.w;
                tu8[0]=b0.x; tu8[1]=b0.y; tu8[2]=b0.z; tu8[3]=b0.w;
                tu8[4]=b1.x; tu8[5]=b1.y; tu8[6]=b1.z; tu8[7]=b1.w;
            }
#pragma unroll
            for (int j = 0; j < SEG; j++) {
                bool te = te8[j] != 0;
                bool tu = tu8[j] != 0;
                float nt = te ? 0.f : 1.f;
                dd[j] = rr[j] + GAMMA_F * nt * nn[j] - vv[j];
                cc[j] = (te || tu) ? 0.f : GL;
            }
        } else {
#pragma unroll
            for (int j = 0; j < SEG; j++) {
                long long idx = base + j;
                if (idx < (long long)n) {
                    bool te, tu;
                    if (byteLayout) {
                        te = ((const uint8_t*)terminated_raw)[idx] != 0;
                        tu = ((const uint8_t*)truncated_raw)[idx] != 0;
                    } else {
                        te = ((const int*)terminated_raw)[idx] != 0;
                        tu = ((const int*)truncated_raw)[idx] != 0;
                    }
                    float nt = te ? 0.f : 1.f;
                    dd[j] = rewards[idx] + GAMMA_F * nt * next_values[idx] - values[idx];
                    cc[j] = (te || tu) ? 0.f : GL;
                } else { cc[j] = 1.f; dd[j] = 0.f; }
            }
        }

        // per-thread segment composition
        float C = 1.f, D = 0.f;
#pragma unroll
        for (int j = SEG - 1; j >= 0; j--) { D = cc[j] * D + dd[j]; C = cc[j] * C; }

        // warp-level inclusive suffix scan via shuffles (5 rounds)
        float iC = C, iD = D;
#pragma unroll
        for (int off = 1; off < 32; off <<= 1) {
            float oc = __shfl_down_sync(0xFFFFFFFFu, iC, off);
            float od = __shfl_down_sync(0xFFFFFFFFu, iD, off);
            float nD = fmaf(iC, od, iD);
            float nC = iC * oc;
            if (lane + off < 32) { iC = nC; iD = nD; }
        }
        // exclusive (value after this thread's segment within warp)
        float eC = __shfl_down_sync(0xFFFFFFFFu, iC, 1);
        float eD = __shfl_down_sync(0xFFFFFFFFu, iD, 1);
        if (lane == 31) { eC = 1.f; eD = 0.f; }

        if (lane == 0) { s_aggC[wrp] = iC; s_aggD[wrp] = iD; }
        __syncthreads();

        if (t == 0) {
            // block aggregate = agg0 o agg1 o ... o agg7
            float bC = 1.f, bD = 0.f;
#pragma unroll
            for (int j = (BLOCK / 32) - 1; j >= 0; j--) {
                bD = fmaf(s_aggC[j], bD, s_aggD[j]);
                bC = s_aggC[j] * bC;
            }
            g_aggC[chunk] = bC; g_aggD[chunk] = bD;
            __threadfence();
            atomicExch(&g_aggFlag[chunk], 1);
            if (bC == 0.f) {
                g_incv[chunk] = bD;
                __threadfence();
                atomicExch(&g_incFlag[chunk], 1);
            }
            float incoming = 0.f;
            if (chunk < numChunks - 1) {
                float aC = 1.f, aD = 0.f;
                int j = chunk + 1;
                for (;;) {
                    if (atomicAdd(&g_incFlag[j], 0) != 0) {
                        __threadfence();
                        incoming = aC * ((volatile float*)g_incv)[j] + aD;
                        break;
                    }
                    if (atomicAdd(&g_aggFlag[j], 0) != 0) {
                        __threadfence();
                        float jc = ((volatile float*)g_aggC)[j];
                        float jd = ((volatile float*)g_aggD)[j];
                        aD = aC * jd + aD;
                        aC = aC * jc;
                        if (aC == 0.f || j == numChunks - 1) { incoming = aD; break; }
                        j++;
                    }
                }
            }
            if (bC != 0.f) {
                g_incv[chunk] = bC * incoming + bD;
                __threadfence();
                atomicExch(&g_incFlag[chunk], 1);
            }
            s_incoming = incoming;
        }
        __syncthreads();

        // warp incoming = agg_{w+1} o ... o agg_7 applied to block incoming
        float win = s_incoming;
        for (int j = (BLOCK / 32) - 1; j > wrp; j--)
            win = fmaf(s_aggC[j], win, s_aggD[j]);

        // x = value right after this thread's segment
        float x = fmaf(eC, win, eD);
        if (full) {
            float outv[SEG];
#pragma unroll
            for (int j = SEG - 1; j >= 0; j--) {
                x = fmaf(cc[j], x, dd[j]);
                outv[j] = x;
                accSum += x; accSq = fmaf(x, x, accSq);
            }
            *(float4*)(g_adv + base)     = make_float4(outv[0], outv[1], outv[2], outv[3]);
            *(float4*)(g_adv + base + 4) = make_float4(outv[4], outv[5], outv[6], outv[7]);
        } else {
#pragma unroll
            for (int j = SEG - 1; j >= 0; j--) {
                x = fmaf(cc[j], x, dd[j]);
                long long idx = base + j;
                if (idx < (long long)n) {
                    g_adv[idx] = x;
                    accSum += x; accSq = fmaf(x, x, accSq);
                }
            }
        }
    }

    // block reduce sums -> global atomics
    {
        double ds = (double)accSum, dq = (double)accSq;
#pragma unroll
        for (int o = 16; o > 0; o >>= 1) {
            ds += __shfl_down_sync(0xFFFFFFFFu, ds, o);
            dq += __shfl_down_sync(0xFFFFFFFFu, dq, o);
        }
        if (lane == 0) { s_wsum[wrp] = ds; s_wsq[wrp] = dq; }
        __syncthreads();
        if (t == 0) {
            double ts = 0.0, tq = 0.0;
#pragma unroll
            for (int w = 0; w < BLOCK / 32; w++) { ts += s_wsum[w]; tq += s_wsq[w]; }
            atomicAdd(&g_sum, ts);
            atomicAdd(&g_sumsq, tq);
        }
    }

    // ===== grid barrier (all GRID blocks co-resident by launch_bounds) =====
    __threadfence();
    if (t == 0) {
        atomicAdd(&g_done, 1);
        while (atomicAdd(&g_done, 0) < GRID) __nanosleep(128);
        __threadfence();
        double s = g_sum, q = g_sumsq;
        double mean = s / (double)n;
        double var = (q - s * s / (double)n) / (double)(n - 1);
        if (var < 0.0) var = 0.0;
        s_mean = (float)mean;
        s_rinv = (float)(1.0 / (sqrt(var) + 1e-9));
    }
    __syncthreads();
    const float mean = s_mean, rinv = s_rinv;

    // ===== phase 2: epilogue =====
    const long long nv4 = n / 4;
    const long long stride = (long long)GRID * BLOCK;
    for (long long i4 = (long long)blockIdx.x * BLOCK + t; i4 < nv4; i4 += stride) {
        long long b4 = i4 * 4;
        float4 a   = *(const float4*)(g_adv + b4);
        float4 v   = __ldcs((const float4*)(values + b4));
        float4 lp  = __ldcs((const float4*)(log_probs + b4));
        float4 olp = __ldcs((const float4*)(old_log_probs + b4));
        float o[12];
        ppo_row(a.x, v.x, lp.x, olp.x, mean, rinv, o + 0);
        ppo_row(a.y, v.y, lp.y, olp.y, mean, rinv, o + 3);
        ppo_row(a.z, v.z, lp.z, olp.z, mean, rinv, o + 6);
        ppo_row(a.w, v.w, lp.w, olp.w, mean, rinv, o + 9);
        float4* dst = (float4*)(out + b4 * 3);
        __stcs(dst + 0, make_float4(o[0], o[1], o[2],  o[3]));
        __stcs(dst + 1, make_float4(o[4], o[5], o[6],  o[7]));
        __stcs(dst + 2, make_float4(o[8], o[9], o[10], o[11]));
    }
    if (blockIdx.x == 0 && t == 0) {
        for (long long i = nv4 * 4; i < (long long)n; i++) {
            float o[3];
            ppo_row(g_adv[i], values[i], log_probs[i], old_log_probs[i], mean, rinv, o);
            out[i * 3 + 0] = o[0];
            out[i * 3 + 1] = o[1];
            out[i * 3 + 2] = o[2];
        }
    }
}

extern "C" void kernel_launch(void* const* d_in, const int* in_sizes, int n_in,
                              void* d_out, int out_size) {
    const float* rewards       = (const float*)d_in[0];
    const float* values        = (const float*)d_in[1];
    const float* next_values   = (const float*)d_in[2];
    const float* log_probs     = (const float*)d_in[3];
    const float* old_log_probs = (const float*)d_in[4];
    const void*  terminated    = d_in[5];
    const void*  truncated     = d_in[6];
    float* out = (float*)d_out;

    int n = in_sizes[0];
    int numChunks = (n + CHUNK - 1) / CHUNK;

    init_kernel<<<(numChunks + 255) / 256, 256>>>((const uint8_t*)terminated,
                                                  (const uint8_t*)truncated, n, numChunks);
    fused_kernel<<<GRID, BLOCK>>>(rewards, values, next_values,
                                  log_probs, old_log_probs,
                                  terminated, truncated, out, n, numChunks);
}